// round 16
// baseline (speedup 1.0000x reference)
#include <cuda_runtime.h>
#include <cuda_bf16.h>
#include <math.h>
#include <stdint.h>

#define NB  8
#define NL  1024
#define ND  512
#define NH  8
#define NHD 64
#define NBH (NB * NH)

// ---------------- static scratch ----------------
__device__ uint32_t g_kq_hi[2][(size_t)NBH * NL * 32];
__device__ uint32_t g_kq_lo[2][(size_t)NBH * NL * 32];
__device__ float    g_v[(size_t)NBH * NL * NHD];
__device__ float    g_r[(size_t)NB * NL * NL];
__device__ float    g_rowsum[(size_t)NBH * NL];
#define SPX (8192 * 256)
#define SPW (512 * 256)
__device__ uint32_t g_sp_hi[3 * SPX + 3 * SPW];
__device__ uint32_t g_sp_lo[3 * SPX + 3 * SPW];

// ---------------- helpers ----------------
__device__ __forceinline__ uint32_t smem_u32(const void* p) {
    uint32_t a;
    asm("{ .reg .u64 t; cvta.to.shared.u64 t, %1; cvt.u32.u64 %0, t; }" : "=r"(a) : "l"(p));
    return a;
}
__device__ __forceinline__ uint32_t packbf(__nv_bfloat16 a, __nv_bfloat16 b) {
    return (uint32_t)__bfloat16_as_ushort(a) | ((uint32_t)__bfloat16_as_ushort(b) << 16);
}
__device__ __forceinline__ uint2 hilo2(float x0, float x1) {
    __nv_bfloat16 h0 = __float2bfloat16(x0), h1 = __float2bfloat16(x1);
    __nv_bfloat16 l0 = __float2bfloat16(x0 - __bfloat162float(h0));
    __nv_bfloat16 l1 = __float2bfloat16(x1 - __bfloat162float(h1));
    return make_uint2(packbf(h0, h1), packbf(l0, l1));
}
__device__ __forceinline__ void split8(float4 a, float4 b, uint4& hi, uint4& lo) {
    uint2 p0 = hilo2(a.x, a.y), p1 = hilo2(a.z, a.w);
    uint2 p2 = hilo2(b.x, b.y), p3 = hilo2(b.z, b.w);
    hi = make_uint4(p0.x, p1.x, p2.x, p3.x);
    lo = make_uint4(p0.y, p1.y, p2.y, p3.y);
}
__device__ __forceinline__ void mma16(float c[4], uint32_t a0, uint32_t a1, uint32_t a2,
                                      uint32_t a3, uint32_t b0, uint32_t b1) {
    asm volatile("mma.sync.aligned.m16n8k16.row.col.f32.bf16.bf16.f32 "
                 "{%0,%1,%2,%3},{%4,%5,%6,%7},{%8,%9},{%0,%1,%2,%3};"
                 : "+f"(c[0]), "+f"(c[1]), "+f"(c[2]), "+f"(c[3])
                 : "r"(a0), "r"(a1), "r"(a2), "r"(a3), "r"(b0), "r"(b1));
}
__device__ __forceinline__ void ldsm4(uint4& r, uint32_t addr) {
    asm volatile("ldmatrix.sync.aligned.m8n8.x4.shared.b16 {%0,%1,%2,%3}, [%4];"
                 : "=r"(r.x), "=r"(r.y), "=r"(r.z), "=r"(r.w) : "r"(addr));
}
#define CP16(dst, src) asm volatile("cp.async.cg.shared.global [%0], [%1], 16;" \
                                    :: "r"(dst), "l"(src) : "memory")
#define CP_COMMIT()    asm volatile("cp.async.commit_group;" ::: "memory")
#define CP_WAIT(n)     asm volatile("cp.async.wait_group %0;" :: "n"(n) : "memory")

#define RSTR 48
#define TA   (128 * RSTR)
#define TB64 (64 * RSTR)
#define PROJ_STAGE (4 * TA)

extern __shared__ char smem[];

// ---------------- block reduction (blockDim == 256) ----------------
__device__ __forceinline__ float2 blk_sum2(float a, float b, float* red) {
    #pragma unroll
    for (int o = 16; o; o >>= 1) {
        a += __shfl_xor_sync(0xffffffffu, a, o);
        b += __shfl_xor_sync(0xffffffffu, b, o);
    }
    int w = threadIdx.x >> 5;
    if ((threadIdx.x & 31) == 0) { red[w] = a; red[w + 8] = b; }
    __syncthreads();
    if (threadIdx.x < 32) {
        float x = (threadIdx.x < 8) ? red[threadIdx.x] : 0.f;
        float y = (threadIdx.x < 8) ? red[threadIdx.x + 8] : 0.f;
        #pragma unroll
        for (int o = 4; o; o >>= 1) {
            x += __shfl_xor_sync(0xffffffffu, x, o);
            y += __shfl_xor_sync(0xffffffffu, y, o);
        }
        if (threadIdx.x == 0) { red[0] = x; red[1] = y; }
    }
    __syncthreads();
    float2 r = make_float2(red[0], red[1]);
    __syncthreads();
    return r;
}

__device__ __forceinline__ uint32_t a_lane_off(int wm, int lane) {
    return (uint32_t)((wm + (lane & 15)) * RSTR + ((lane >> 4) << 4));
}
__device__ __forceinline__ uint32_t b_lane_off(int wn, int lane) {
    return (uint32_t)((wn + ((lane >> 4) << 3) + (lane & 7)) * RSTR + (((lane >> 3) & 1) << 4));
}

// =============== K0: presplit proj inputs ===============
__global__ void __launch_bounds__(256) presplit_kernel(
    const float* __restrict__ q, const float* __restrict__ k, const float* __restrict__ v,
    const float* __restrict__ wq, const float* __restrict__ wk, const float* __restrict__ wv)
{
    const int ten = blockIdx.y;
    const float* src = (ten == 0) ? q : (ten == 1) ? k : (ten == 2) ? v
                     : (ten == 3) ? wq : (ten == 4) ? wk : wv;
    const size_t nquad = (ten < 3) ? (size_t)SPX / 4 : (size_t)SPW / 4;
    const size_t base = (ten < 3) ? (size_t)ten * SPX
                                  : (size_t)3 * SPX + (size_t)(ten - 3) * SPW;
    const size_t i = (size_t)blockIdx.x * 256 + threadIdx.x;
    if (i >= nquad) return;
    float4 a = *(const float4*)(src + i * 8);
    float4 b = *(const float4*)(src + i * 8 + 4);
    uint4 h, l;
    split8(a, b, h, l);
    *(uint4*)(g_sp_hi + base + i * 4) = h;
    *(uint4*)(g_sp_lo + base + i * 4) = l;
}

// =============== K1: projection GEMM (R13: 256 thr, warp 64x32, BK=16, 3-stage) ===============
__global__ void __launch_bounds__(256, 2) proj_mma_kernel(
    const float* __restrict__ bqp, const float* __restrict__ bkp, const float* __restrict__ bvp)
{
    const int which = blockIdx.z;
    const float* bias = (which == 0) ? bqp : (which == 1) ? bkp : bvp;

    const uint32_t sb = smem_u32(smem);
    const int t = threadIdx.x, lane = t & 31, warp = t >> 5;
    const int wm = (warp & 1) * 64, wn = (warp >> 1) * 32;
    const int m0 = blockIdx.x * 128, n0 = blockIdx.y * 128;
    const int frow = t >> 1, fh = t & 1;

    const uint32_t* Ah = g_sp_hi + (size_t)which * SPX + (size_t)(m0 + frow) * 256 + fh * 4;
    const uint32_t* Al = g_sp_lo + (size_t)which * SPX + (size_t)(m0 + frow) * 256 + fh * 4;
    const uint32_t* Bh = g_sp_hi + 3 * (size_t)SPX + (size_t)which * SPW + (size_t)(n0 + frow) * 256 + fh * 4;
    const uint32_t* Bl = g_sp_lo + 3 * (size_t)SPX + (size_t)which * SPW + (size_t)(n0 + frow) * 256 + fh * 4;

    float acc[4][4][4];
    #pragma unroll
    for (int i = 0; i < 4; i++)
        #pragma unroll
        for (int j = 0; j < 4; j++)
            #pragma unroll
            for (int k = 0; k < 4; k++) acc[i][j][k] = 0.f;

    auto fill = [&](int s, int ks) {
        const uint32_t d = sb + s * PROJ_STAGE + frow * RSTR + fh * 16;
        CP16(d,          Ah + ks * 8);
        CP16(d + TA,     Al + ks * 8);
        CP16(d + 2 * TA, Bh + ks * 8);
        CP16(d + 3 * TA, Bl + ks * 8);
    };

    fill(0, 0); CP_COMMIT();
    fill(1, 1); CP_COMMIT();

    const uint32_t ao = a_lane_off(wm, lane);
    const uint32_t bo = b_lane_off(wn, lane);

    const int NK = ND / 16;
    for (int ks = 0; ks < NK; ks++) {
        CP_WAIT(1);
        __syncthreads();
        if (ks + 2 < NK) fill((ks + 2) % 3, ks + 2);
        CP_COMMIT();
        const uint32_t sa = sb + (ks % 3) * PROJ_STAGE;
        uint4 afh[4], bfh[2], bfl[2], afl[4];
        #pragma unroll
        for (int mi = 0; mi < 4; mi++) ldsm4(afh[mi], sa + ao + mi * (16 * RSTR));
        #pragma unroll
        for (int j = 0; j < 2; j++) ldsm4(bfh[j], sa + 2 * TA + bo + j * (16 * RSTR));
        #pragma unroll
        for (int j = 0; j < 2; j++)
            #pragma unroll
            for (int mi = 0; mi < 4; mi++) {
                mma16(acc[mi][2 * j],     afh[mi].x, afh[mi].y, afh[mi].z, afh[mi].w, bfh[j].x, bfh[j].y);
                mma16(acc[mi][2 * j + 1], afh[mi].x, afh[mi].y, afh[mi].z, afh[mi].w, bfh[j].z, bfh[j].w);
            }
        #pragma unroll
        for (int j = 0; j < 2; j++) ldsm4(bfl[j], sa + 3 * TA + bo + j * (16 * RSTR));
        #pragma unroll
        for (int j = 0; j < 2; j++)
            #pragma unroll
            for (int mi = 0; mi < 4; mi++) {
                mma16(acc[mi][2 * j],     afh[mi].x, afh[mi].y, afh[mi].z, afh[mi].w, bfl[j].x, bfl[j].y);
                mma16(acc[mi][2 * j + 1], afh[mi].x, afh[mi].y, afh[mi].z, afh[mi].w, bfl[j].z, bfl[j].w);
            }
        #pragma unroll
        for (int mi = 0; mi < 4; mi++) ldsm4(afl[mi], sa + TA + ao + mi * (16 * RSTR));
        #pragma unroll
        for (int j = 0; j < 2; j++)
            #pragma unroll
            for (int mi = 0; mi < 4; mi++) {
                mma16(acc[mi][2 * j],     afl[mi].x, afl[mi].y, afl[mi].z, afl[mi].w, bfh[j].x, bfh[j].y);
                mma16(acc[mi][2 * j + 1], afl[mi].x, afl[mi].y, afl[mi].z, afl[mi].w, bfh[j].z, bfh[j].w);
            }
        __syncthreads();
    }

    const int b = m0 >> 10;
    if (which < 2) {
        uint32_t* Hp = g_kq_hi[which];
        uint32_t* Lp = g_kq_lo[which];
        #pragma unroll
        for (int ni = 0; ni < 4; ni++) {
            const int n = n0 + wn + ni * 8 + (lane & 3) * 2;
            const float2 bb = *(const float2*)(bias + n);
            const int h = n >> 6, w = (n & 63) >> 1;
            const size_t base = (((size_t)(b * NH + h) * NL) << 5) + w;
            #pragma unroll
            for (int mi = 0; mi < 4; mi++) {
                const int l = (m0 & (NL - 1)) + wm + mi * 16 + (lane >> 2);
                uint2 hl = hilo2(acc[mi][ni][0] + bb.x, acc[mi][ni][1] + bb.y);
                Hp[base + ((size_t)l << 5)] = hl.x;
                Lp[base + ((size_t)l << 5)] = hl.y;
                hl = hilo2(acc[mi][ni][2] + bb.x, acc[mi][ni][3] + bb.y);
                Hp[base + ((size_t)(l + 8) << 5)] = hl.x;
                Lp[base + ((size_t)(l + 8) << 5)] = hl.y;
            }
        }
    } else {
        #pragma unroll
        for (int ni = 0; ni < 4; ni++) {
            const int n = n0 + wn + ni * 8 + (lane & 3) * 2;
            const float2 bb = *(const float2*)(bias + n);
            const int h = n >> 6, hd = n & 63;
            float* obase = g_v + (((size_t)(b * NH + h) * NL) << 6) + hd;
            #pragma unroll
            for (int mi = 0; mi < 4; mi++) {
                const int l = (m0 & (NL - 1)) + wm + mi * 16 + (lane >> 2);
                *(float2*)(obase + ((size_t)l << 6)) =
                    make_float2(acc[mi][ni][0] + bb.x, acc[mi][ni][1] + bb.y);
                *(float2*)(obase + ((size_t)(l + 8) << 6)) =
                    make_float2(acc[mi][ni][2] + bb.x, acc[mi][ni][3] + bb.y);
            }
        }
    }
}

// =============== K3: scores — 128x64 tiles, 3 CTAs/SM (occupancy push) ===============
// grid (128, NBH): bx = qt*16 + kn (kn = 64-col tile). kn > 2*qt+1 -> zero fill.
// smem: QH c at c*TA, QL at (4+c)*TA  [48KB]; K base 8*TA: KH c at +c*TB64, KL at +(4+c)*TB64 [24KB].
__global__ void __launch_bounds__(256, 3) scores_mma_kernel(float* __restrict__ p)
{
    const int bx = blockIdx.x;
    const int qt = bx >> 4, kn = bx & 15;
    const int bh = blockIdx.y;
    const int t = threadIdx.x;
    float* pb = p + ((size_t)bh * NL + qt * 128) * NL + kn * 64;

    if (kn > 2 * qt + 1) {   // fully masked 128x64 tile: zero fill
        const float4 z = make_float4(0.f, 0.f, 0.f, 0.f);
        #pragma unroll
        for (int i = 0; i < 8; i++) {
            const int f = i * 256 + t;            // flat float4 index, 16 per row
            *(float4*)(pb + (size_t)(f >> 4) * NL + ((f & 15) << 2)) = z;
        }
        return;
    }

    const uint32_t sb = smem_u32(smem);
    const int lane = t & 31, warp = t >> 5;
    const int wm = (warp & 3) * 32, wn = (warp >> 2) * 32;

    // fill Q (128 rows x 64 cols, hi+lo) and K (64 rows x 64 cols, hi+lo)
    {
        const int frow = t >> 1, fh = t & 1;
        const size_t qoff = (((size_t)bh * NL + qt * 128 + frow) << 5) + fh * 4;
        const uint32_t* Qh = g_kq_hi[0] + qoff;
        const uint32_t* Ql = g_kq_lo[0] + qoff;
        #pragma unroll
        for (int c = 0; c < 4; c++) {
            const uint32_t dA = sb + c * TA + frow * RSTR + fh * 16;
            CP16(dA,          Qh + 8 * c);
            CP16(dA + 4 * TA, Ql + 8 * c);
        }
        const int kr = t >> 2, kp = t & 3;       // row 0..63, tile chunk 0..3
        const size_t koff = ((size_t)bh * NL + kn * 64 + kr) << 5;
        const uint32_t* Kh = g_kq_hi[1] + koff + kp * 8;
        const uint32_t* Kl = g_kq_lo[1] + koff + kp * 8;
        const uint32_t dK = sb + 8 * TA + kp * TB64 + kr * RSTR;
        CP16(dK,               Kh);
        CP16(dK + 16,          Kh + 4);
        CP16(dK + 4 * TB64,    Kl);
        CP16(dK + 4 * TB64 + 16, Kl + 4);
        CP_COMMIT();
        CP_WAIT(0);
    }
    __syncthreads();

    const uint32_t ao = a_lane_off(wm, lane);
    const uint32_t bo = b_lane_off(wn, lane);

    float acc[2][4][4];
    #pragma unroll
    for (int i = 0; i < 2; i++)
        #pragma unroll
        for (int j = 0; j < 4; j++)
            #pragma unroll
            for (int k = 0; k < 4; k++) acc[i][j][k] = 0.f;

    #pragma unroll
    for (int c = 0; c < 4; c++) {
        const uint32_t sA  = sb + c * TA;
        const uint32_t sAl = sA + 4 * TA;
        const uint32_t sB  = sb + 8 * TA + c * TB64;
        const uint32_t sBl = sB + 4 * TB64;
        uint4 afh[2], bfh[2], bfl[2], afl[2];
        #pragma unroll
        for (int mi = 0; mi < 2; mi++) ldsm4(afh[mi], sA + ao + mi * (16 * RSTR));
        #pragma unroll
        for (int j = 0; j < 2; j++) ldsm4(bfh[j], sB + bo + j * (16 * RSTR));
        #pragma unroll
        for (int j = 0; j < 2; j++)
            #pragma unroll
            for (int mi = 0; mi < 2; mi++) {
                mma16(acc[mi][2 * j],     afh[mi].x, afh[mi].y, afh[mi].z, afh[mi].w, bfh[j].x, bfh[j].y);
                mma16(acc[mi][2 * j + 1], afh[mi].x, afh[mi].y, afh[mi].z, afh[mi].w, bfh[j].z, bfh[j].w);
            }
        #pragma unroll
        for (int j = 0; j < 2; j++) ldsm4(bfl[j], sBl + bo + j * (16 * RSTR));
        #pragma unroll
        for (int j = 0; j < 2; j++)
            #pragma unroll
            for (int mi = 0; mi < 2; mi++) {
                mma16(acc[mi][2 * j],     afh[mi].x, afh[mi].y, afh[mi].z, afh[mi].w, bfl[j].x, bfl[j].y);
                mma16(acc[mi][2 * j + 1], afh[mi].x, afh[mi].y, afh[mi].z, afh[mi].w, bfl[j].z, bfl[j].w);
            }
        #pragma unroll
        for (int mi = 0; mi < 2; mi++) ldsm4(afl[mi], sAl + ao + mi * (16 * RSTR));
        #pragma unroll
        for (int j = 0; j < 2; j++)
            #pragma unroll
            for (int mi = 0; mi < 2; mi++) {
                mma16(acc[mi][2 * j],     afl[mi].x, afl[mi].y, afl[mi].z, afl[mi].w, bfh[j].x, bfh[j].y);
                mma16(acc[mi][2 * j + 1], afl[mi].x, afl[mi].y, afl[mi].z, afl[mi].w, bfh[j].z, bfh[j].w);
            }
    }

    // epilogue: causal mask, e = exp(s/8), rowsum atomics, store e
    const int colbase = kn * 64 + wn + (lane & 3) * 2;
    const int rowbase = qt * 128 + wm + (lane >> 2);
    #pragma unroll
    for (int mi = 0; mi < 2; mi++) {
        const int r0 = rowbase + mi * 16, r1 = r0 + 8;
        float rs0 = 0.f, rs1 = 0.f;
        #pragma unroll
        for (int ni = 0; ni < 4; ni++) {
            const int col = colbase + ni * 8;
            float e0 = (col     <= r0) ? __expf(acc[mi][ni][0] * 0.125f) : 0.f;
            float e1 = (col + 1 <= r0) ? __expf(acc[mi][ni][1] * 0.125f) : 0.f;
            float e2 = (col     <= r1) ? __expf(acc[mi][ni][2] * 0.125f) : 0.f;
            float e3 = (col + 1 <= r1) ? __expf(acc[mi][ni][3] * 0.125f) : 0.f;
            acc[mi][ni][0] = e0; acc[mi][ni][1] = e1;
            acc[mi][ni][2] = e2; acc[mi][ni][3] = e3;
            rs0 += e0 + e1; rs1 += e2 + e3;
        }
        #pragma unroll
        for (int off = 1; off <= 2; off <<= 1) {
            rs0 += __shfl_xor_sync(0xffffffffu, rs0, off);
            rs1 += __shfl_xor_sync(0xffffffffu, rs1, off);
        }
        if ((lane & 3) == 0) {
            atomicAdd(&g_rowsum[(size_t)bh * NL + r0], rs0);
            atomicAdd(&g_rowsum[(size_t)bh * NL + r1], rs1);
        }
    }
    #pragma unroll
    for (int ni = 0; ni < 4; ni++) {
        const int col = wn + ni * 8 + (lane & 3) * 2;
        #pragma unroll
        for (int mi = 0; mi < 2; mi++) {
            const int row = wm + mi * 16 + (lane >> 2);
            *(float2*)(pb + (size_t)row * NL + col) =
                make_float2(acc[mi][ni][0], acc[mi][ni][1]);
            *(float2*)(pb + (size_t)(row + 8) * NL + col) =
                make_float2(acc[mi][ni][2], acc[mi][ni][3]);
        }
    }
}

// =============== K4: blend2 — reduction-free:  p = c0/rowsum * e + r  (in place) ===============
__global__ void __launch_bounds__(256) blend2_kernel(float* __restrict__ p,
                                                     const float* __restrict__ pl1,
                                                     const float* __restrict__ pl2) {
    const int bhq = blockIdx.x;
    const int q = bhq & (NL - 1);
    float* prow = p + (size_t)bhq * NL;
    const int k4 = threadIdx.x << 2;
    if (q == 0) {
        *(float4*)(prow + k4) = make_float4(0.f, 0.f, 0.f, 0.f);
        return;
    }
    if (k4 > q) return;   // upper region already exact zeros from scores
    const float L1 = *pl1, L2 = *pl2;
    const float c0 = (1.f - L1) * (1.f - L2) / g_rowsum[bhq];
    const int b = bhq >> 13;
    float4 e = *(const float4*)(prow + k4);
    const float4 r = *(const float4*)(g_r + ((size_t)b * NL + q) * NL + k4);
    const bool v1 = k4 + 1 <= q, v2 = k4 + 2 <= q, v3 = k4 + 3 <= q;
    float4 o;
    o.x = fmaf(c0, e.x, r.x);
    o.y = v1 ? fmaf(c0, e.y, r.y) : 0.f;
    o.z = v2 ? fmaf(c0, e.z, r.z) : 0.f;
    o.w = v3 ? fmaf(c0, e.w, r.w) : 0.f;
    *(float4*)(prow + k4) = o;
}

// =============== K5: out = p @ v ===============
__global__ void __launch_bounds__(256, 2) pv_mma_kernel(const float* __restrict__ p,
                                                        float* __restrict__ out)
{
    const int qt = 7 - blockIdx.x;
    const int bh = blockIdx.y;

    const uint32_t sb = smem_u32(smem);
    const int t = threadIdx.x, lane = t & 31, warp = t >> 5;
    const int wm = (warp & 3) * 32, wn = (warp >> 2) * 32;
    const int frow = t >> 1, fh = t & 1;
    const int vn = t & 63, vg = t >> 6;

    const float* Ag = p + ((size_t)bh * NL + qt * 128 + frow) * NL + fh * 8;
    const float* Vg = g_v + (size_t)bh * NL * NHD + vn;

    float acc[2][4][4];
    #pragma unroll
    for (int i = 0; i < 2; i++)
        #pragma unroll
        for (int j = 0; j < 4; j++)
            #pragma unroll
            for (int k = 0; k < 4; k++) acc[i][j][k] = 0.f;

    float4 ra0, ra1;
    float rv[4];
    auto gload = [&](int ks) {
        ra0 = *(const float4*)(Ag + ks * 16);
        ra1 = *(const float4*)(Ag + ks * 16 + 4);
        const float* vbase = Vg + (size_t)(ks * 16 + vg * 4) * NHD;
        rv[0] = vbase[0]; rv[1] = vbase[NHD]; rv[2] = vbase[2 * NHD]; rv[3] = vbase[3 * NHD];
    };
    auto store_tile = [&](int buf) {
        char* base = smem + buf * 18432;
        uint4 h, l;
        split8(ra0, ra1, h, l);
        *(uint4*)(base + frow * RSTR + fh * 16) = h;
        *(uint4*)(base + TA + frow * RSTR + fh * 16) = l;
        uint2 p0 = hilo2(rv[0], rv[1]), p1 = hilo2(rv[2], rv[3]);
        *(uint2*)(base + 2 * TA + vn * RSTR + vg * 8) = make_uint2(p0.x, p1.x);
        *(uint2*)(base + 2 * TA + TB64 + vn * RSTR + vg * 8) = make_uint2(p0.y, p1.y);
    };
    gload(0);
    store_tile(0);
    __syncthreads();

    const uint32_t ao = a_lane_off(wm, lane);
    const uint32_t bo = b_lane_off(wn, lane);

    const int NK = (qt + 1) * 8;
    int buf = 0;
    for (int ks = 0; ks < NK; ks++) {
        if (ks + 1 < NK) gload(ks + 1);
        const uint32_t sa = sb + buf * 18432;
        uint4 afh[2], bfh[2], bfl[2], afl[2];
        #pragma unroll
        for (int mi = 0; mi < 2; mi++) ldsm4(afh[mi], sa + ao + mi * (16 * RSTR));
        #pragma unroll
        for (int j = 0; j < 2; j++) ldsm4(bfh[j], sa + 2 * TA + bo + j * (16 * RSTR));
        #pragma unroll
        for (int j = 0; j < 2; j++)
            #pragma unroll
            for (int mi = 0; mi < 2; mi++) {
                mma16(acc[mi][2 * j],     afh[mi].x, afh[mi].y, afh[mi].z, afh[mi].w, bfh[j].x, bfh[j].y);
                mma16(acc[mi][2 * j + 1], afh[mi].x, afh[mi].y, afh[mi].z, afh[mi].w, bfh[j].z, bfh[j].w);
            }
        #pragma unroll
        for (int j = 0; j < 2; j++) ldsm4(bfl[j], sa + 2 * TA + TB64 + bo + j * (16 * RSTR));
        #pragma unroll
        for (int j = 0; j < 2; j++)
            #pragma unroll
            for (int mi = 0; mi < 2; mi++) {
                mma16(acc[mi][2 * j],     afh[mi].x, afh[mi].y, afh[mi].z, afh[mi].w, bfl[j].x, bfl[j].y);
                mma16(acc[mi][2 * j + 1], afh[mi].x, afh[mi].y, afh[mi].z, afh[mi].w, bfl[j].z, bfl[j].w);
            }
        #pragma unroll
        for (int mi = 0; mi < 2; mi++) ldsm4(afl[mi], sa + TA + ao + mi * (16 * RSTR));
        #pragma unroll
        for (int j = 0; j < 2; j++)
            #pragma unroll
            for (int mi = 0; mi < 2; mi++) {
                mma16(acc[mi][2 * j],     afl[mi].x, afl[mi].y, afl[mi].z, afl[mi].w, bfh[j].x, bfh[j].y);
                mma16(acc[mi][2 * j + 1], afl[mi].x, afl[mi].y, afl[mi].z, afl[mi].w, bfh[j].z, bfh[j].w);
            }
        if (ks + 1 < NK) { store_tile(buf ^ 1); buf ^= 1; }
        __syncthreads();
    }

    const int b = bh >> 3, h = bh & 7;
    #pragma unroll
    for (int ni = 0; ni < 4; ni++) {
        const int hd = wn + ni * 8 + (lane & 3) * 2;
        #pragma unroll
        for (int mi = 0; mi < 2; mi++) {
            const int l = qt * 128 + wm + mi * 16 + (lane >> 2);
            float* o = out + ((size_t)(b * NL) + l) * ND + h * 64 + hd;
            *(float2*)o = make_float2(acc[mi][ni][0], acc[mi][ni][1]);
            *(float2*)(o + (size_t)8 * ND) = make_float2(acc[mi][ni][2], acc[mi][ni][3]);
        }
    }
}

// =============== K2: base (+ rowsum zero-init) ===============
__global__ void __launch_bounds__(256) base_kernel(const float* __restrict__ rel,
                                                   const float* __restrict__ ts,
                                                   const float* __restrict__ pl1,
                                                   const float* __restrict__ pl2) {
    __shared__ float red[32];
    const int bq = blockIdx.x;
    const int q = bq & (NL - 1);
    const size_t roff = (size_t)bq * NL;
    const int tid = threadIdx.x;
    const int k4 = tid << 2;

    if (tid < 8) g_rowsum[((size_t)bq << 3) + tid] = 0.f;

    float4 e1 = make_float4(0.f, 0.f, 0.f, 0.f);
    float4 e2 = make_float4(0.f, 0.f, 0.f, 0.f);
    if (k4 <= q) {
        float4 rv = *(const float4*)(rel + roff + k4);
        float4 tsv = *(const float4*)(ts + roff + k4);
        const bool v1 = k4 + 1 <= q, v2 = k4 + 2 <= q, v3 = k4 + 3 <= q;
        e1.x = __expf(rv.x);
        e1.y = v1 ? __expf(rv.y) : 0.f;
        e1.z = v2 ? __expf(rv.z) : 0.f;
        e1.w = v3 ? __expf(rv.w) : 0.f;
        e2.x = __expf(__expf(-fabsf(tsv.x)));
        e2.y = v1 ? __expf(__expf(-fabsf(tsv.y))) : 0.f;
        e2.z = v2 ? __expf(__expf(-fabsf(tsv.z))) : 0.f;
        e2.w = v3 ? __expf(__expf(-fabsf(tsv.w))) : 0.f;
    }
    float2 s = blk_sum2(e1.x + e1.y + e1.z + e1.w, e2.x + e2.y + e2.z + e2.w, red);

    if (k4 <= q) {
        const float L1 = *pl1, L2 = *pl2;
        const float c1 = L1 * (1.f - L2) / s.x;
        const float c2 = L2 / s.y;
        float4 o;
        o.x = c1 * e1.x + c2 * e2.x;
        o.y = c1 * e1.y + c2 * e2.y;
        o.z = c1 * e1.z + c2 * e2.z;
        o.w = c1 * e1.w + c2 * e2.w;
        *(float4*)(g_r + roff + k4) = o;
    }
}

// ---------------- entry point ----------------
extern "C" void kernel_launch(void* const* d_in, const int* in_sizes, int n_in,
                              void* d_out, int out_size) {
    const float* query  = (const float*)d_in[0];
    const float* key    = (const float*)d_in[1];
    const float* value  = (const float*)d_in[2];
    const float* rel    = (const float*)d_in[3];
    const float* l1     = (const float*)d_in[4];
    const float* l2     = (const float*)d_in[5];
    const float* tstamp = (const float*)d_in[6];
    const float* Wq = (const float*)d_in[8];
    const float* bq = (const float*)d_in[9];
    const float* Wk = (const float*)d_in[10];
    const float* bk = (const float*)d_in[11];
    const float* Wv = (const float*)d_in[12];
    const float* bv = (const float*)d_in[13];

    float* out  = (float*)d_out;
    float* pout = out + (size_t)NB * NL * ND;

    const int SMEM_PROJ = 3 * PROJ_STAGE;          // 73728
    const int SMEM_SC   = 8 * TA + 8 * TB64;       // 73728 (3 CTAs/SM)
    const int SMEM_PV   = 2 * 18432;               // 36864
    cudaFuncSetAttribute(proj_mma_kernel,   cudaFuncAttributeMaxDynamicSharedMemorySize, SMEM_PROJ);
    cudaFuncSetAttribute(scores_mma_kernel, cudaFuncAttributeMaxDynamicSharedMemorySize, SMEM_SC);
    cudaFuncSetAttribute(pv_mma_kernel,     cudaFuncAttributeMaxDynamicSharedMemorySize, SMEM_PV);

    presplit_kernel<<<dim3(2048, 6), 256>>>(query, key, value, Wq, Wk, Wv);
    proj_mma_kernel<<<dim3(64, 4, 3), 256, SMEM_PROJ>>>(bq, bk, bv);
    base_kernel<<<NB * NL, 256>>>(rel, tstamp, l1, l2);
    scores_mma_kernel<<<dim3(128, NBH), 256, SMEM_SC>>>(pout);
    blend2_kernel<<<NBH * NL, 256>>>(pout, l1, l2);
    pv_mma_kernel<<<dim3(8, NBH), 256, SMEM_PV>>>(pout, out);
}

// round 17
// speedup vs baseline: 1.0850x; 1.0850x over previous
#include <cuda_runtime.h>
#include <cuda_bf16.h>
#include <cuda_fp16.h>
#include <math.h>
#include <stdint.h>

#define NB  8
#define NL  1024
#define ND  512
#define NH  8
#define NHD 64
#define NBH (NB * NH)

// ---------------- static scratch ----------------
// Q: single fp16 plane in g_kq_hi[0].  K: fp16 hi/lo in g_kq_hi[1]/g_kq_lo[1].
__device__ uint32_t g_kq_hi[2][(size_t)NBH * NL * 32];
__device__ uint32_t g_kq_lo[2][(size_t)NBH * NL * 32];
__device__ float    g_v[(size_t)NBH * NL * NHD];
__device__ float    g_r[(size_t)NB * NL * NL];
__device__ float    g_rowsum[(size_t)NBH * NL];
#define SPX (8192 * 256)
#define SPW (512 * 256)
__device__ uint32_t g_sp_hi[3 * SPX + 3 * SPW];
__device__ uint32_t g_sp_lo[3 * SPX + 3 * SPW];

// ---------------- helpers ----------------
__device__ __forceinline__ uint32_t smem_u32(const void* p) {
    uint32_t a;
    asm("{ .reg .u64 t; cvta.to.shared.u64 t, %1; cvt.u32.u64 %0, t; }" : "=r"(a) : "l"(p));
    return a;
}
__device__ __forceinline__ uint32_t packbf(__nv_bfloat16 a, __nv_bfloat16 b) {
    return (uint32_t)__bfloat16_as_ushort(a) | ((uint32_t)__bfloat16_as_ushort(b) << 16);
}
__device__ __forceinline__ uint2 hilo2(float x0, float x1) {   // bf16 hi/lo (proj inputs)
    __nv_bfloat16 h0 = __float2bfloat16(x0), h1 = __float2bfloat16(x1);
    __nv_bfloat16 l0 = __float2bfloat16(x0 - __bfloat162float(h0));
    __nv_bfloat16 l1 = __float2bfloat16(x1 - __bfloat162float(h1));
    return make_uint2(packbf(h0, h1), packbf(l0, l1));
}
__device__ __forceinline__ void split8(float4 a, float4 b, uint4& hi, uint4& lo) {
    uint2 p0 = hilo2(a.x, a.y), p1 = hilo2(a.z, a.w);
    uint2 p2 = hilo2(b.x, b.y), p3 = hilo2(b.z, b.w);
    hi = make_uint4(p0.x, p1.x, p2.x, p3.x);
    lo = make_uint4(p0.y, p1.y, p2.y, p3.y);
}
// fp16 helpers
__device__ __forceinline__ uint32_t pack2h(float x0, float x1) {
    __half h0 = __float2half_rn(x0), h1 = __float2half_rn(x1);
    return (uint32_t)__half_as_ushort(h0) | ((uint32_t)__half_as_ushort(h1) << 16);
}
__device__ __forceinline__ uint2 hilo2h(float x0, float x1) {
    __half h0 = __float2half_rn(x0), h1 = __float2half_rn(x1);
    __half l0 = __float2half_rn(x0 - __half2float(h0));
    __half l1 = __float2half_rn(x1 - __half2float(h1));
    return make_uint2((uint32_t)__half_as_ushort(h0) | ((uint32_t)__half_as_ushort(h1) << 16),
                      (uint32_t)__half_as_ushort(l0) | ((uint32_t)__half_as_ushort(l1) << 16));
}
// bf16 mma (proj)
__device__ __forceinline__ void mma16(float c[4], uint32_t a0, uint32_t a1, uint32_t a2,
                                      uint32_t a3, uint32_t b0, uint32_t b1) {
    asm volatile("mma.sync.aligned.m16n8k16.row.col.f32.bf16.bf16.f32 "
                 "{%0,%1,%2,%3},{%4,%5,%6,%7},{%8,%9},{%0,%1,%2,%3};"
                 : "+f"(c[0]), "+f"(c[1]), "+f"(c[2]), "+f"(c[3])
                 : "r"(a0), "r"(a1), "r"(a2), "r"(a3), "r"(b0), "r"(b1));
}
// fp16 mma (scores, pv)
__device__ __forceinline__ void mma16h(float c[4], uint32_t a0, uint32_t a1, uint32_t a2,
                                       uint32_t a3, uint32_t b0, uint32_t b1) {
    asm volatile("mma.sync.aligned.m16n8k16.row.col.f32.f16.f16.f32 "
                 "{%0,%1,%2,%3},{%4,%5,%6,%7},{%8,%9},{%0,%1,%2,%3};"
                 : "+f"(c[0]), "+f"(c[1]), "+f"(c[2]), "+f"(c[3])
                 : "r"(a0), "r"(a1), "r"(a2), "r"(a3), "r"(b0), "r"(b1));
}
__device__ __forceinline__ void ldsm4(uint4& r, uint32_t addr) {
    asm volatile("ldmatrix.sync.aligned.m8n8.x4.shared.b16 {%0,%1,%2,%3}, [%4];"
                 : "=r"(r.x), "=r"(r.y), "=r"(r.z), "=r"(r.w) : "r"(addr));
}
#define CP16(dst, src) asm volatile("cp.async.cg.shared.global [%0], [%1], 16;" \
                                    :: "r"(dst), "l"(src) : "memory")
#define CP_COMMIT()    asm volatile("cp.async.commit_group;" ::: "memory")
#define CP_WAIT(n)     asm volatile("cp.async.wait_group %0;" :: "n"(n) : "memory")

#define RSTR 48
#define TA   (128 * RSTR)
#define TB64 (64 * RSTR)
#define PROJ_STAGE (4 * TA)
#define PV_STAGE (TA + 2 * TB64)   // 12288: p(fp16) + Vhi + Vlo

extern __shared__ char smem[];

// ---------------- block reduction (blockDim == 256) ----------------
__device__ __forceinline__ float2 blk_sum2(float a, float b, float* red) {
    #pragma unroll
    for (int o = 16; o; o >>= 1) {
        a += __shfl_xor_sync(0xffffffffu, a, o);
        b += __shfl_xor_sync(0xffffffffu, b, o);
    }
    int w = threadIdx.x >> 5;
    if ((threadIdx.x & 31) == 0) { red[w] = a; red[w + 8] = b; }
    __syncthreads();
    if (threadIdx.x < 32) {
        float x = (threadIdx.x < 8) ? red[threadIdx.x] : 0.f;
        float y = (threadIdx.x < 8) ? red[threadIdx.x + 8] : 0.f;
        #pragma unroll
        for (int o = 4; o; o >>= 1) {
            x += __shfl_xor_sync(0xffffffffu, x, o);
            y += __shfl_xor_sync(0xffffffffu, y, o);
        }
        if (threadIdx.x == 0) { red[0] = x; red[1] = y; }
    }
    __syncthreads();
    float2 r = make_float2(red[0], red[1]);
    __syncthreads();
    return r;
}

__device__ __forceinline__ uint32_t a_lane_off(int wm, int lane) {
    return (uint32_t)((wm + (lane & 15)) * RSTR + ((lane >> 4) << 4));
}
__device__ __forceinline__ uint32_t b_lane_off(int wn, int lane) {
    return (uint32_t)((wn + ((lane >> 4) << 3) + (lane & 7)) * RSTR + (((lane >> 3) & 1) << 4));
}

// =============== K0: presplit proj inputs (bf16 hi/lo, unchanged) ===============
__global__ void __launch_bounds__(256) presplit_kernel(
    const float* __restrict__ q, const float* __restrict__ k, const float* __restrict__ v,
    const float* __restrict__ wq, const float* __restrict__ wk, const float* __restrict__ wv)
{
    const int ten = blockIdx.y;
    const float* src = (ten == 0) ? q : (ten == 1) ? k : (ten == 2) ? v
                     : (ten == 3) ? wq : (ten == 4) ? wk : wv;
    const size_t nquad = (ten < 3) ? (size_t)SPX / 4 : (size_t)SPW / 4;
    const size_t base = (ten < 3) ? (size_t)ten * SPX
                                  : (size_t)3 * SPX + (size_t)(ten - 3) * SPW;
    const size_t i = (size_t)blockIdx.x * 256 + threadIdx.x;
    if (i >= nquad) return;
    float4 a = *(const float4*)(src + i * 8);
    float4 b = *(const float4*)(src + i * 8 + 4);
    uint4 h, l;
    split8(a, b, h, l);
    *(uint4*)(g_sp_hi + base + i * 4) = h;
    *(uint4*)(g_sp_lo + base + i * 4) = l;
}

// =============== K1: projection GEMM (bf16 3-product, R13) ===============
__global__ void __launch_bounds__(256, 2) proj_mma_kernel(
    const float* __restrict__ bqp, const float* __restrict__ bkp, const float* __restrict__ bvp)
{
    const int which = blockIdx.z;
    const float* bias = (which == 0) ? bqp : (which == 1) ? bkp : bvp;

    const uint32_t sb = smem_u32(smem);
    const int t = threadIdx.x, lane = t & 31, warp = t >> 5;
    const int wm = (warp & 1) * 64, wn = (warp >> 1) * 32;
    const int m0 = blockIdx.x * 128, n0 = blockIdx.y * 128;
    const int frow = t >> 1, fh = t & 1;

    const uint32_t* Ah = g_sp_hi + (size_t)which * SPX + (size_t)(m0 + frow) * 256 + fh * 4;
    const uint32_t* Al = g_sp_lo + (size_t)which * SPX + (size_t)(m0 + frow) * 256 + fh * 4;
    const uint32_t* Bh = g_sp_hi + 3 * (size_t)SPX + (size_t)which * SPW + (size_t)(n0 + frow) * 256 + fh * 4;
    const uint32_t* Bl = g_sp_lo + 3 * (size_t)SPX + (size_t)which * SPW + (size_t)(n0 + frow) * 256 + fh * 4;

    float acc[4][4][4];
    #pragma unroll
    for (int i = 0; i < 4; i++)
        #pragma unroll
        for (int j = 0; j < 4; j++)
            #pragma unroll
            for (int k = 0; k < 4; k++) acc[i][j][k] = 0.f;

    auto fill = [&](int s, int ks) {
        const uint32_t d = sb + s * PROJ_STAGE + frow * RSTR + fh * 16;
        CP16(d,          Ah + ks * 8);
        CP16(d + TA,     Al + ks * 8);
        CP16(d + 2 * TA, Bh + ks * 8);
        CP16(d + 3 * TA, Bl + ks * 8);
    };

    fill(0, 0); CP_COMMIT();
    fill(1, 1); CP_COMMIT();

    const uint32_t ao = a_lane_off(wm, lane);
    const uint32_t bo = b_lane_off(wn, lane);

    const int NK = ND / 16;
    for (int ks = 0; ks < NK; ks++) {
        CP_WAIT(1);
        __syncthreads();
        if (ks + 2 < NK) fill((ks + 2) % 3, ks + 2);
        CP_COMMIT();
        const uint32_t sa = sb + (ks % 3) * PROJ_STAGE;
        uint4 afh[4], bfh[2], bfl[2], afl[4];
        #pragma unroll
        for (int mi = 0; mi < 4; mi++) ldsm4(afh[mi], sa + ao + mi * (16 * RSTR));
        #pragma unroll
        for (int j = 0; j < 2; j++) ldsm4(bfh[j], sa + 2 * TA + bo + j * (16 * RSTR));
        #pragma unroll
        for (int j = 0; j < 2; j++)
            #pragma unroll
            for (int mi = 0; mi < 4; mi++) {
                mma16(acc[mi][2 * j],     afh[mi].x, afh[mi].y, afh[mi].z, afh[mi].w, bfh[j].x, bfh[j].y);
                mma16(acc[mi][2 * j + 1], afh[mi].x, afh[mi].y, afh[mi].z, afh[mi].w, bfh[j].z, bfh[j].w);
            }
        #pragma unroll
        for (int j = 0; j < 2; j++) ldsm4(bfl[j], sa + 3 * TA + bo + j * (16 * RSTR));
        #pragma unroll
        for (int j = 0; j < 2; j++)
            #pragma unroll
            for (int mi = 0; mi < 4; mi++) {
                mma16(acc[mi][2 * j],     afh[mi].x, afh[mi].y, afh[mi].z, afh[mi].w, bfl[j].x, bfl[j].y);
                mma16(acc[mi][2 * j + 1], afh[mi].x, afh[mi].y, afh[mi].z, afh[mi].w, bfl[j].z, bfl[j].w);
            }
        #pragma unroll
        for (int mi = 0; mi < 4; mi++) ldsm4(afl[mi], sa + TA + ao + mi * (16 * RSTR));
        #pragma unroll
        for (int j = 0; j < 2; j++)
            #pragma unroll
            for (int mi = 0; mi < 4; mi++) {
                mma16(acc[mi][2 * j],     afl[mi].x, afl[mi].y, afl[mi].z, afl[mi].w, bfh[j].x, bfh[j].y);
                mma16(acc[mi][2 * j + 1], afl[mi].x, afl[mi].y, afl[mi].z, afl[mi].w, bfh[j].z, bfh[j].w);
            }
        __syncthreads();
    }

    const int b = m0 >> 10;
    if (which == 0) {
        // Q: single fp16 plane
        uint32_t* Hp = g_kq_hi[0];
        #pragma unroll
        for (int ni = 0; ni < 4; ni++) {
            const int n = n0 + wn + ni * 8 + (lane & 3) * 2;
            const float2 bb = *(const float2*)(bias + n);
            const int h = n >> 6, w = (n & 63) >> 1;
            const size_t base = (((size_t)(b * NH + h) * NL) << 5) + w;
            #pragma unroll
            for (int mi = 0; mi < 4; mi++) {
                const int l = (m0 & (NL - 1)) + wm + mi * 16 + (lane >> 2);
                Hp[base + ((size_t)l << 5)] = pack2h(acc[mi][ni][0] + bb.x, acc[mi][ni][1] + bb.y);
                Hp[base + ((size_t)(l + 8) << 5)] = pack2h(acc[mi][ni][2] + bb.x, acc[mi][ni][3] + bb.y);
            }
        }
    } else if (which == 1) {
        // K: fp16 hi/lo planes
        uint32_t* Hp = g_kq_hi[1];
        uint32_t* Lp = g_kq_lo[1];
        #pragma unroll
        for (int ni = 0; ni < 4; ni++) {
            const int n = n0 + wn + ni * 8 + (lane & 3) * 2;
            const float2 bb = *(const float2*)(bias + n);
            const int h = n >> 6, w = (n & 63) >> 1;
            const size_t base = (((size_t)(b * NH + h) * NL) << 5) + w;
            #pragma unroll
            for (int mi = 0; mi < 4; mi++) {
                const int l = (m0 & (NL - 1)) + wm + mi * 16 + (lane >> 2);
                uint2 hl = hilo2h(acc[mi][ni][0] + bb.x, acc[mi][ni][1] + bb.y);
                Hp[base + ((size_t)l << 5)] = hl.x;
                Lp[base + ((size_t)l << 5)] = hl.y;
                hl = hilo2h(acc[mi][ni][2] + bb.x, acc[mi][ni][3] + bb.y);
                Hp[base + ((size_t)(l + 8) << 5)] = hl.x;
                Lp[base + ((size_t)(l + 8) << 5)] = hl.y;
            }
        }
    } else {
        #pragma unroll
        for (int ni = 0; ni < 4; ni++) {
            const int n = n0 + wn + ni * 8 + (lane & 3) * 2;
            const float2 bb = *(const float2*)(bias + n);
            const int h = n >> 6, hd = n & 63;
            float* obase = g_v + (((size_t)(b * NH + h) * NL) << 6) + hd;
            #pragma unroll
            for (int mi = 0; mi < 4; mi++) {
                const int l = (m0 & (NL - 1)) + wm + mi * 16 + (lane >> 2);
                *(float2*)(obase + ((size_t)l << 6)) =
                    make_float2(acc[mi][ni][0] + bb.x, acc[mi][ni][1] + bb.y);
                *(float2*)(obase + ((size_t)(l + 8) << 6)) =
                    make_float2(acc[mi][ni][2] + bb.x, acc[mi][ni][3] + bb.y);
            }
        }
    }
}

// =============== K3: scores — fp16 2-product (Q single, K hi/lo) ===============
// grid (64, NBH): bx = qt*8 + kt; kt>qt CTAs zero-fill.
// smem: Q c at c*TA (c=0..3), Kh at (4+c)*TA, Kl at (8+c)*TA  -> 12*TA = 73728.
__global__ void __launch_bounds__(256, 2) scores_mma_kernel(float* __restrict__ p)
{
    const int bx = blockIdx.x;
    const int qt = bx >> 3, kt = bx & 7;
    const int bh = blockIdx.y;
    const int t = threadIdx.x;
    float* pb = p + ((size_t)bh * NL + qt * 128) * NL + kt * 128;

    if (kt > qt) {
        const float4 z = make_float4(0.f, 0.f, 0.f, 0.f);
        #pragma unroll
        for (int i = 0; i < 16; i++) {
            const int f = i * 256 + t;
            *(float4*)(pb + (size_t)(f >> 5) * NL + ((f & 31) << 2)) = z;
        }
        return;
    }

    const uint32_t sb = smem_u32(smem);
    const int lane = t & 31, warp = t >> 5;
    const int wm = (warp & 1) * 64, wn = (warp >> 1) * 32;
    const int frow = t >> 1, fh = t & 1;

    {
        const size_t qoff = (((size_t)bh * NL + qt * 128 + frow) << 5) + fh * 4;
        const size_t koff = (((size_t)bh * NL + kt * 128 + frow) << 5) + fh * 4;
        const uint32_t* Qp = g_kq_hi[0] + qoff;
        const uint32_t* Kh = g_kq_hi[1] + koff;
        const uint32_t* Kl = g_kq_lo[1] + koff;
        #pragma unroll
        for (int c = 0; c < 4; c++) {
            const uint32_t d = sb + frow * RSTR + fh * 16;
            CP16(d + c * TA,       Qp + 8 * c);
            CP16(d + (4 + c) * TA, Kh + 8 * c);
            CP16(d + (8 + c) * TA, Kl + 8 * c);
        }
        CP_COMMIT();
        CP_WAIT(0);
    }
    __syncthreads();

    const uint32_t ao = a_lane_off(wm, lane);
    const uint32_t bo = b_lane_off(wn, lane);

    float acc[4][4][4];
    #pragma unroll
    for (int i = 0; i < 4; i++)
        #pragma unroll
        for (int j = 0; j < 4; j++)
            #pragma unroll
            for (int k = 0; k < 4; k++) acc[i][j][k] = 0.f;

    #pragma unroll
    for (int c = 0; c < 4; c++) {
        const uint32_t sQ  = sb + c * TA;
        const uint32_t sKh = sb + (4 + c) * TA;
        const uint32_t sKl = sb + (8 + c) * TA;
        uint4 af[4], bfh[2], bfl[2];
        #pragma unroll
        for (int mi = 0; mi < 4; mi++) ldsm4(af[mi], sQ + ao + mi * (16 * RSTR));
        #pragma unroll
        for (int j = 0; j < 2; j++) ldsm4(bfh[j], sKh + bo + j * (16 * RSTR));
        #pragma unroll
        for (int j = 0; j < 2; j++)
            #pragma unroll
            for (int mi = 0; mi < 4; mi++) {
                mma16h(acc[mi][2 * j],     af[mi].x, af[mi].y, af[mi].z, af[mi].w, bfh[j].x, bfh[j].y);
                mma16h(acc[mi][2 * j + 1], af[mi].x, af[mi].y, af[mi].z, af[mi].w, bfh[j].z, bfh[j].w);
            }
        #pragma unroll
        for (int j = 0; j < 2; j++) ldsm4(bfl[j], sKl + bo + j * (16 * RSTR));
        #pragma unroll
        for (int j = 0; j < 2; j++)
            #pragma unroll
            for (int mi = 0; mi < 4; mi++) {
                mma16h(acc[mi][2 * j],     af[mi].x, af[mi].y, af[mi].z, af[mi].w, bfl[j].x, bfl[j].y);
                mma16h(acc[mi][2 * j + 1], af[mi].x, af[mi].y, af[mi].z, af[mi].w, bfl[j].z, bfl[j].w);
            }
    }

    const int colbase = kt * 128 + wn + (lane & 3) * 2;
    const int rowbase = qt * 128 + wm + (lane >> 2);
    #pragma unroll
    for (int mi = 0; mi < 4; mi++) {
        const int r0 = rowbase + mi * 16, r1 = r0 + 8;
        float rs0 = 0.f, rs1 = 0.f;
        #pragma unroll
        for (int ni = 0; ni < 4; ni++) {
            const int col = colbase + ni * 8;
            float e0 = (col     <= r0) ? __expf(acc[mi][ni][0] * 0.125f) : 0.f;
            float e1 = (col + 1 <= r0) ? __expf(acc[mi][ni][1] * 0.125f) : 0.f;
            float e2 = (col     <= r1) ? __expf(acc[mi][ni][2] * 0.125f) : 0.f;
            float e3 = (col + 1 <= r1) ? __expf(acc[mi][ni][3] * 0.125f) : 0.f;
            acc[mi][ni][0] = e0; acc[mi][ni][1] = e1;
            acc[mi][ni][2] = e2; acc[mi][ni][3] = e3;
            rs0 += e0 + e1; rs1 += e2 + e3;
        }
        #pragma unroll
        for (int off = 1; off <= 2; off <<= 1) {
            rs0 += __shfl_xor_sync(0xffffffffu, rs0, off);
            rs1 += __shfl_xor_sync(0xffffffffu, rs1, off);
        }
        if ((lane & 3) == 0) {
            atomicAdd(&g_rowsum[(size_t)bh * NL + r0], rs0);
            atomicAdd(&g_rowsum[(size_t)bh * NL + r1], rs1);
        }
    }
    #pragma unroll
    for (int ni = 0; ni < 4; ni++) {
        const int col = wn + ni * 8 + (lane & 3) * 2;
        #pragma unroll
        for (int mi = 0; mi < 4; mi++) {
            const int row = wm + mi * 16 + (lane >> 2);
            *(float2*)(pb + (size_t)row * NL + col) =
                make_float2(acc[mi][ni][0], acc[mi][ni][1]);
            *(float2*)(pb + (size_t)(row + 8) * NL + col) =
                make_float2(acc[mi][ni][2], acc[mi][ni][3]);
        }
    }
}

// =============== K4: blend2 — reduction-free (unchanged) ===============
__global__ void __launch_bounds__(256) blend2_kernel(float* __restrict__ p,
                                                     const float* __restrict__ pl1,
                                                     const float* __restrict__ pl2) {
    const int bhq = blockIdx.x;
    const int q = bhq & (NL - 1);
    float* prow = p + (size_t)bhq * NL;
    const int k4 = threadIdx.x << 2;
    if (q == 0) {
        *(float4*)(prow + k4) = make_float4(0.f, 0.f, 0.f, 0.f);
        return;
    }
    if (k4 > q) return;
    const float L1 = *pl1, L2 = *pl2;
    const float c0 = (1.f - L1) * (1.f - L2) / g_rowsum[bhq];
    const int b = bhq >> 13;
    float4 e = *(const float4*)(prow + k4);
    const float4 r = *(const float4*)(g_r + ((size_t)b * NL + q) * NL + k4);
    const bool v1 = k4 + 1 <= q, v2 = k4 + 2 <= q, v3 = k4 + 3 <= q;
    float4 o;
    o.x = fmaf(c0, e.x, r.x);
    o.y = v1 ? fmaf(c0, e.y, r.y) : 0.f;
    o.z = v2 ? fmaf(c0, e.z, r.z) : 0.f;
    o.w = v3 ? fmaf(c0, e.w, r.w) : 0.f;
    *(float4*)(prow + k4) = o;
}

// =============== K5: pv — fp16 2-product (p single, V hi/lo) ===============
__global__ void __launch_bounds__(256, 2) pv_mma_kernel(const float* __restrict__ p,
                                                        float* __restrict__ out)
{
    const int qt = 7 - blockIdx.x;
    const int bh = blockIdx.y;

    const uint32_t sb = smem_u32(smem);
    const int t = threadIdx.x, lane = t & 31, warp = t >> 5;
    const int wm = (warp & 3) * 32, wn = (warp >> 2) * 32;
    const int frow = t >> 1, fh = t & 1;
    const int vn = t & 63, vg = t >> 6;

    const float* Ag = p + ((size_t)bh * NL + qt * 128 + frow) * NL + fh * 8;
    const float* Vg = g_v + (size_t)bh * NL * NHD + vn;

    float acc[2][4][4];
    #pragma unroll
    for (int i = 0; i < 2; i++)
        #pragma unroll
        for (int j = 0; j < 4; j++)
            #pragma unroll
            for (int k = 0; k < 4; k++) acc[i][j][k] = 0.f;

    float4 ra0, ra1;
    float rv[4];
    auto gload = [&](int ks) {
        ra0 = *(const float4*)(Ag + ks * 16);
        ra1 = *(const float4*)(Ag + ks * 16 + 4);
        const float* vbase = Vg + (size_t)(ks * 16 + vg * 4) * NHD;
        rv[0] = vbase[0]; rv[1] = vbase[NHD]; rv[2] = vbase[2 * NHD]; rv[3] = vbase[3 * NHD];
    };
    auto store_tile = [&](int buf) {
        char* base = smem + buf * PV_STAGE;
        uint4 ph;
        ph.x = pack2h(ra0.x, ra0.y); ph.y = pack2h(ra0.z, ra0.w);
        ph.z = pack2h(ra1.x, ra1.y); ph.w = pack2h(ra1.z, ra1.w);
        *(uint4*)(base + frow * RSTR + fh * 16) = ph;
        uint2 v01 = hilo2h(rv[0], rv[1]), v23 = hilo2h(rv[2], rv[3]);
        *(uint2*)(base + TA + vn * RSTR + vg * 8) = make_uint2(v01.x, v23.x);
        *(uint2*)(base + TA + TB64 + vn * RSTR + vg * 8) = make_uint2(v01.y, v23.y);
    };
    gload(0);
    store_tile(0);
    __syncthreads();

    const uint32_t ao = a_lane_off(wm, lane);
    const uint32_t bo = b_lane_off(wn, lane);

    const int NK = (qt + 1) * 8;
    int buf = 0;
    for (int ks = 0; ks < NK; ks++) {
        if (ks + 1 < NK) gload(ks + 1);
        const uint32_t sa = sb + buf * PV_STAGE;
        uint4 af[2], bfh[2], bfl[2];
        #pragma unroll
        for (int mi = 0; mi < 2; mi++) ldsm4(af[mi], sa + ao + mi * (16 * RSTR));
        #pragma unroll
        for (int j = 0; j < 2; j++) ldsm4(bfh[j], sa + TA + bo + j * (16 * RSTR));
        #pragma unroll
        for (int j = 0; j < 2; j++)
            #pragma unroll
            for (int mi = 0; mi < 2; mi++) {
                mma16h(acc[mi][2 * j],     af[mi].x, af[mi].y, af[mi].z, af[mi].w, bfh[j].x, bfh[j].y);
                mma16h(acc[mi][2 * j + 1], af[mi].x, af[mi].y, af[mi].z, af[mi].w, bfh[j].z, bfh[j].w);
            }
        #pragma unroll
        for (int j = 0; j < 2; j++) ldsm4(bfl[j], sa + TA + TB64 + bo + j * (16 * RSTR));
        #pragma unroll
        for (int j = 0; j < 2; j++)
            #pragma unroll
            for (int mi = 0; mi < 2; mi++) {
                mma16h(acc[mi][2 * j],     af[mi].x, af[mi].y, af[mi].z, af[mi].w, bfl[j].x, bfl[j].y);
                mma16h(acc[mi][2 * j + 1], af[mi].x, af[mi].y, af[mi].z, af[mi].w, bfl[j].z, bfl[j].w);
            }
        if (ks + 1 < NK) { store_tile(buf ^ 1); buf ^= 1; }
        __syncthreads();
    }

    const int b = bh >> 3, h = bh & 7;
    #pragma unroll
    for (int ni = 0; ni < 4; ni++) {
        const int hd = wn + ni * 8 + (lane & 3) * 2;
        #pragma unroll
        for (int mi = 0; mi < 2; mi++) {
            const int l = qt * 128 + wm + mi * 16 + (lane >> 2);
            float* o = out + ((size_t)(b * NL) + l) * ND + h * 64 + hd;
            *(float2*)o = make_float2(acc[mi][ni][0], acc[mi][ni][1]);
            *(float2*)(o + (size_t)8 * ND) = make_float2(acc[mi][ni][2], acc[mi][ni][3]);
        }
    }
}

// =============== K2: base (+ rowsum zero-init, unchanged) ===============
__global__ void __launch_bounds__(256) base_kernel(const float* __restrict__ rel,
                                                   const float* __restrict__ ts,
                                                   const float* __restrict__ pl1,
                                                   const float* __restrict__ pl2) {
    __shared__ float red[32];
    const int bq = blockIdx.x;
    const int q = bq & (NL - 1);
    const size_t roff = (size_t)bq * NL;
    const int tid = threadIdx.x;
    const int k4 = tid << 2;

    if (tid < 8) g_rowsum[((size_t)bq << 3) + tid] = 0.f;

    float4 e1 = make_float4(0.f, 0.f, 0.f, 0.f);
    float4 e2 = make_float4(0.f, 0.f, 0.f, 0.f);
    if (k4 <= q) {
        float4 rv = *(const float4*)(rel + roff + k4);
        float4 tsv = *(const float4*)(ts + roff + k4);
        const bool v1 = k4 + 1 <= q, v2 = k4 + 2 <= q, v3 = k4 + 3 <= q;
        e1.x = __expf(rv.x);
        e1.y = v1 ? __expf(rv.y) : 0.f;
        e1.z = v2 ? __expf(rv.z) : 0.f;
        e1.w = v3 ? __expf(rv.w) : 0.f;
        e2.x = __expf(__expf(-fabsf(tsv.x)));
        e2.y = v1 ? __expf(__expf(-fabsf(tsv.y))) : 0.f;
        e2.z = v2 ? __expf(__expf(-fabsf(tsv.z))) : 0.f;
        e2.w = v3 ? __expf(__expf(-fabsf(tsv.w))) : 0.f;
    }
    float2 s = blk_sum2(e1.x + e1.y + e1.z + e1.w, e2.x + e2.y + e2.z + e2.w, red);

    if (k4 <= q) {
        const float L1 = *pl1, L2 = *pl2;
        const float c1 = L1 * (1.f - L2) / s.x;
        const float c2 = L2 / s.y;
        float4 o;
        o.x = c1 * e1.x + c2 * e2.x;
        o.y = c1 * e1.y + c2 * e2.y;
        o.z = c1 * e1.z + c2 * e2.z;
        o.w = c1 * e1.w + c2 * e2.w;
        *(float4*)(g_r + roff + k4) = o;
    }
}

// ---------------- entry point ----------------
extern "C" void kernel_launch(void* const* d_in, const int* in_sizes, int n_in,
                              void* d_out, int out_size) {
    const float* query  = (const float*)d_in[0];
    const float* key    = (const float*)d_in[1];
    const float* value  = (const float*)d_in[2];
    const float* rel    = (const float*)d_in[3];
    const float* l1     = (const float*)d_in[4];
    const float* l2     = (const float*)d_in[5];
    const float* tstamp = (const float*)d_in[6];
    const float* Wq = (const float*)d_in[8];
    const float* bq = (const float*)d_in[9];
    const float* Wk = (const float*)d_in[10];
    const float* bk = (const float*)d_in[11];
    const float* Wv = (const float*)d_in[12];
    const float* bv = (const float*)d_in[13];

    float* out  = (float*)d_out;
    float* pout = out + (size_t)NB * NL * ND;

    const int SMEM_PROJ = 3 * PROJ_STAGE;  // 73728
    const int SMEM_SC   = 12 * TA;         // 73728
    const int SMEM_PV   = 2 * PV_STAGE;    // 24576
    cudaFuncSetAttribute(proj_mma_kernel,   cudaFuncAttributeMaxDynamicSharedMemorySize, SMEM_PROJ);
    cudaFuncSetAttribute(scores_mma_kernel, cudaFuncAttributeMaxDynamicSharedMemorySize, SMEM_SC);
    cudaFuncSetAttribute(pv_mma_kernel,     cudaFuncAttributeMaxDynamicSharedMemorySize, SMEM_PV);

    presplit_kernel<<<dim3(2048, 6), 256>>>(query, key, value, Wq, Wk, Wv);
    proj_mma_kernel<<<dim3(64, 4, 3), 256, SMEM_PROJ>>>(bq, bk, bv);
    base_kernel<<<NB * NL, 256>>>(rel, tstamp, l1, l2);
    scores_mma_kernel<<<dim3(64, NBH), 256, SMEM_SC>>>(pout);
    blend2_kernel<<<NBH * NL, 256>>>(pout, l1, l2);
    pv_mma_kernel<<<dim3(8, NBH), 256, SMEM_PV>>>(pout, out);
}